// round 1
// baseline (speedup 1.0000x reference)
#include <cuda_runtime.h>

#define NNODE 20000
#define NU    512
#define NE    81920
#define NBAT  8
#define NC    64

// ---------------- device scratch (no allocation allowed) ----------------
__device__ int   g_idx64;
__device__ int   g_deg[NNODE];
__device__ int   g_rowstart[NNODE + 1];
__device__ int   g_cursor[NNODE];
__device__ int   g_perm[NE];
__device__ int   g_edgestart[NU + 1];
__device__ float g_si[NNODE * NBAT];          // x . att_i  per (node,b)
__device__ float g_sj[NU * NBAT];             // edge_result . att_j per (u,b)
__device__ float g_agg[NBAT * NU * NC];       // [b][u][c]
__device__ float g_q[NBAT * NU * NC];
__device__ float g_k[NBAT * NU * NC];
__device__ float g_vj[NBAT * NU];             // v . att_j per (b,u)
__device__ float g_wv[NC];                    // Wv^T att_j
__device__ float g_cv;                        // bv . att_j
__device__ float g_alpha[NE * NBAT];          // [e][b]
__device__ float g_out1[NU * NBAT * NC];      // [u][b][c]

// index accessors: handle int32 or int64 hyperedge_index
__device__ __forceinline__ int nodeAt(const int* hi, int e, int is64) {
    return is64 ? hi[2 * e] : hi[e];
}
__device__ __forceinline__ int edgeAt(const int* hi, int e, int is64) {
    return is64 ? hi[2 * (NE + e)] : hi[NE + e];
}

// ---------------- setup ----------------
__global__ void k_detect(const int* hi) {
    if (threadIdx.x == 0) {
        int odd_or = 0;
        for (int i = 0; i < 64; i++) odd_or |= hi[2 * i + 1];
        g_idx64 = (odd_or == 0) ? 1 : 0;   // int64 little-endian -> high words 0
    }
}

__global__ void k_zero_deg() {
    int i = blockIdx.x * blockDim.x + threadIdx.x;
    if (i < NNODE) g_deg[i] = 0;
}

// degree histogram + hyperedge segment boundaries (edges input is sorted)
__global__ void k_hist(const int* hi) {
    int i = blockIdx.x * blockDim.x + threadIdx.x;
    if (i >= NE) return;
    int is64 = g_idx64;
    int n = nodeAt(hi, i, is64);
    atomicAdd(&g_deg[n], 1);
    int u  = edgeAt(hi, i, is64);
    int up = (i == 0) ? -1 : edgeAt(hi, i - 1, is64);
    if (u != up) g_edgestart[u] = i;
    if (i == NE - 1) g_edgestart[NU] = NE;
}

// single-block exclusive scan over node degrees -> CSR row starts
__global__ void k_scan() {
    __shared__ int wsum[32];
    int tid = threadIdx.x, lane = tid & 31, wid = tid >> 5;
    int carry = 0;
    for (int base = 0; base < NNODE; base += 1024) {
        int i = base + tid;
        int v = (i < NNODE) ? g_deg[i] : 0;
        int x = v;
        #pragma unroll
        for (int o = 1; o < 32; o <<= 1) {
            int y = __shfl_up_sync(0xffffffffu, x, o);
            if (lane >= o) x += y;
        }
        if (lane == 31) wsum[wid] = x;
        __syncthreads();
        if (wid == 0) {
            int t = wsum[lane];
            #pragma unroll
            for (int o = 1; o < 32; o <<= 1) {
                int y = __shfl_up_sync(0xffffffffu, t, o);
                if (lane >= o) t += y;
            }
            wsum[lane] = t;
        }
        __syncthreads();
        int winc  = (wid == 0) ? 0 : wsum[wid - 1];
        int incl  = x + winc;
        int total = wsum[31];
        int excl  = carry + incl - v;
        if (i < NNODE) { g_rowstart[i] = excl; g_cursor[i] = excl; }
        carry += total;
        __syncthreads();
    }
    if (tid == 0) g_rowstart[NNODE] = carry;
}

__global__ void k_scatter(const int* hi) {
    int e = blockIdx.x * blockDim.x + threadIdx.x;
    if (e >= NE) return;
    int n = nodeAt(hi, e, g_idx64);
    int pos = atomicAdd(&g_cursor[n], 1);
    g_perm[pos] = e;
}

// ---------------- s_i = x . att_i : one warp per (node, b) ----------------
__global__ void k_si(const float* __restrict__ x, const float* __restrict__ att) {
    int n = blockIdx.x;
    int b = threadIdx.x >> 5;
    int lane = threadIdx.x & 31;
    const float* row = x + ((size_t)b * NNODE + n) * NC;
    float v = row[lane] * att[lane] + row[lane + 32] * att[lane + 32];
    #pragma unroll
    for (int o = 16; o; o >>= 1) v += __shfl_down_sync(0xffffffffu, v, o);
    if (lane == 0) g_si[n * NBAT + b] = v;
}

// ---------------- agg[u,b,c] = sum over incidences of x[b,node,c] ----------------
__global__ void k_agg(const float* __restrict__ x, const int* __restrict__ hi) {
    int u = blockIdx.x;
    int start = g_edgestart[u], end = g_edgestart[u + 1];
    int b = threadIdx.x >> 6, c = threadIdx.x & 63;
    int is64 = g_idx64;
    __shared__ int nidx[256];
    float acc = 0.f;
    for (int s0 = start; s0 < end; s0 += 256) {
        int cnt = min(256, end - s0);
        __syncthreads();
        if ((int)threadIdx.x < cnt) nidx[threadIdx.x] = nodeAt(hi, s0 + threadIdx.x, is64);
        __syncthreads();
        for (int j = 0; j < cnt; j++)
            acc += x[((size_t)b * NNODE + nidx[j]) * NC + c];
    }
    g_agg[(b * NU + u) * NC + c] = acc;
}

// ---------------- wv_eff = Wv^T att_j ; cv = bv . att_j ----------------
__global__ void k_weff(const float* __restrict__ Wv, const float* __restrict__ bv,
                       const float* __restrict__ att) {
    int k = threadIdx.x;
    float w = 0.f;
    for (int c = 0; c < NC; c++) w += Wv[c * NC + k] * att[NC + c];
    g_wv[k] = w;
    if (k == 0) {
        float cv = 0.f;
        for (int c = 0; c < NC; c++) cv += bv[c] * att[NC + c];
        g_cv = cv;
    }
}

// ---------------- q, k projections: 32 u-rows per block ----------------
__global__ void k_qk(const float* __restrict__ Wq, const float* __restrict__ bq,
                     const float* __restrict__ Wk, const float* __restrict__ bk) {
    int b  = blockIdx.y;
    int u0 = blockIdx.x * 32;
    __shared__ float wq_s[64][65];
    __shared__ float wk_s[64][65];
    __shared__ float agg_s[4][65];
    for (int i = threadIdx.x; i < 4096; i += 256) {
        int c = i >> 6, k = i & 63;
        wq_s[c][k] = Wq[i];
        wk_s[c][k] = Wk[i];
    }
    __syncthreads();
    int r = threadIdx.x >> 6, c = threadIdx.x & 63;
    for (int r0 = 0; r0 < 32; r0 += 4) {
        __syncthreads();
        agg_s[r][c] = g_agg[(b * NU + u0 + r0 + r) * NC + c];
        __syncthreads();
        float qa = bq[c], ka = bk[c];
        #pragma unroll
        for (int k = 0; k < 64; k++) {
            float a = agg_s[r][k];
            qa += a * wq_s[c][k];
            ka += a * wk_s[c][k];
        }
        int u = u0 + r0 + r;
        g_q[(b * NU + u) * NC + c] = qa;
        g_k[(b * NU + u) * NC + c] = ka;
    }
}

// ---------------- vj[b,u] = agg . wv_eff + cv : one warp per (b,u) ----------------
__global__ void k_vj() {
    int gw = blockIdx.x * (blockDim.x >> 5) + (threadIdx.x >> 5);
    int lane = threadIdx.x & 31;
    int b = gw >> 9, u = gw & 511;
    const float* row = g_agg + (b * NU + u) * NC;
    float v = row[lane] * g_wv[lane] + row[lane + 32] * g_wv[lane + 32];
    #pragma unroll
    for (int o = 16; o; o >>= 1) v += __shfl_down_sync(0xffffffffu, v, o);
    if (lane == 0) g_vj[b * NU + u] = v + g_cv;
}

// ---------------- masked attention: scores+softmax fused into s_j ----------------
__global__ void k_attn(const float* __restrict__ adj) {
    extern __shared__ float sm[];
    float* q_s  = sm;                  // 32*65
    float* k_s  = q_s + 32 * 65;       // 64*65
    float* vj_s = k_s + 64 * 65;       // 512
    float* sc   = vj_s + 512;          // 32*512

    int b  = blockIdx.y;
    int u0 = blockIdx.x * 32;
    int tid = threadIdx.x;

    for (int i = tid; i < 2048; i += 256) {
        int u = i >> 6, c = i & 63;
        q_s[u * 65 + c] = g_q[(b * NU + u0 + u) * NC + c];
    }
    for (int i = tid; i < 512; i += 256) vj_s[i] = g_vj[b * NU + i];
    __syncthreads();

    int ug = (tid & 7) * 4;
    int v0 = (tid >> 3) * 2;
    for (int ch = 0; ch < 8; ch++) {
        __syncthreads();
        for (int i = tid; i < 4096; i += 256) {
            int v = i >> 6, c = i & 63;
            k_s[v * 65 + c] = g_k[(b * NU + ch * 64 + v) * NC + c];
        }
        __syncthreads();
        float acc[4][2] = {{0.f, 0.f}, {0.f, 0.f}, {0.f, 0.f}, {0.f, 0.f}};
        #pragma unroll
        for (int k = 0; k < 64; k++) {
            float kv0 = k_s[v0 * 65 + k];
            float kv1 = k_s[(v0 + 1) * 65 + k];
            #pragma unroll
            for (int i = 0; i < 4; i++) {
                float qv = q_s[(ug + i) * 65 + k];
                acc[i][0] += qv * kv0;
                acc[i][1] += qv * kv1;
            }
        }
        #pragma unroll
        for (int i = 0; i < 4; i++)
            #pragma unroll
            for (int j = 0; j < 2; j++) {
                int u = ug + i, v = ch * 64 + v0 + j;
                float a = adj[(size_t)(u0 + u) * NU + v];
                sc[u * 512 + v] = acc[i][j] * 0.125f - (1.0f - a) * 500.0f;
            }
    }
    __syncthreads();

    // softmax + dot with vj, per row; warp handles 4 rows
    int wid = tid >> 5, lane = tid & 31;
    for (int rr = 0; rr < 4; rr++) {
        int u = wid * 4 + rr;
        float m = -1e30f;
        for (int v = lane; v < 512; v += 32) m = fmaxf(m, sc[u * 512 + v]);
        #pragma unroll
        for (int o = 16; o; o >>= 1) m = fmaxf(m, __shfl_xor_sync(0xffffffffu, m, o));
        float s = 0.f, d = 0.f;
        for (int v = lane; v < 512; v += 32) {
            float ex = __expf(sc[u * 512 + v] - m);
            s += ex;
            d += ex * vj_s[v];
        }
        #pragma unroll
        for (int o = 16; o; o >>= 1) {
            s += __shfl_xor_sync(0xffffffffu, s, o);
            d += __shfl_xor_sync(0xffffffffu, d, o);
        }
        if (lane == 0) g_sj[(u0 + u) * NBAT + b] = d / s;
    }
}

// ---------------- raw alpha per (e,b) ----------------
__global__ void k_alpha_raw(const int* __restrict__ hi) {
    int idx = blockIdx.x * blockDim.x + threadIdx.x;   // NE*8 total
    int e = idx >> 3, b = idx & 7;
    int is64 = g_idx64;
    int n = nodeAt(hi, e, is64);
    int u = edgeAt(hi, e, is64);
    float a = g_si[n * NBAT + b] + g_sj[u * NBAT + b];
    a = (a > 0.f) ? a : 0.2f * a;
    g_alpha[idx] = a;
}

// ---------------- node-segment softmax on alpha (via node CSR) ----------------
__global__ void k_nodesm() {
    int idx = blockIdx.x * blockDim.x + threadIdx.x;   // NNODE*8 total
    if (idx >= NNODE * NBAT) return;
    int n = idx >> 3, b = idx & 7;
    int s = g_rowstart[n], e2 = g_rowstart[n + 1];
    if (s == e2) return;
    float m = -1e30f;
    for (int j = s; j < e2; j++) m = fmaxf(m, g_alpha[g_perm[j] * NBAT + b]);
    float sum = 0.f;
    for (int j = s; j < e2; j++) sum += __expf(g_alpha[g_perm[j] * NBAT + b] - m);
    float inv = 1.0f / (sum + 1e-16f);
    for (int j = s; j < e2; j++) {
        int o = g_perm[j] * NBAT + b;
        g_alpha[o] = __expf(g_alpha[o] - m) * inv;
    }
}

// ---------------- stage 1: out1[u,b,c] = (1/deg_e) sum alpha * x ----------------
__global__ void k_out1(const float* __restrict__ x, const int* __restrict__ hi) {
    int u = blockIdx.x;
    int start = g_edgestart[u], end = g_edgestart[u + 1];
    float bn = (end > start) ? 1.0f / (float)(end - start) : 0.0f;
    int b = threadIdx.x >> 6, c = threadIdx.x & 63;
    int is64 = g_idx64;
    __shared__ int nidx[256];
    __shared__ float a_s[256 * 8];
    float acc = 0.f;
    for (int s0 = start; s0 < end; s0 += 256) {
        int cnt = min(256, end - s0);
        __syncthreads();
        for (int i = threadIdx.x; i < cnt; i += 512) nidx[i] = nodeAt(hi, s0 + i, is64);
        for (int i = threadIdx.x; i < cnt * 8; i += 512) a_s[i] = g_alpha[s0 * 8 + i];
        __syncthreads();
        for (int j = 0; j < cnt; j++)
            acc += a_s[j * 8 + b] * x[((size_t)b * NNODE + nidx[j]) * NC + c];
    }
    g_out1[(u * NBAT + b) * NC + c] = acc * bn;
}

// ---------------- stage 2: out[b,n,c] = D[n] * sum alpha * out1[edge] ----------------
__global__ void k_out2(const int* __restrict__ hi, float* __restrict__ out) {
    int n = blockIdx.x;
    int s = g_rowstart[n], e2 = g_rowstart[n + 1];
    int b = threadIdx.x >> 6, c = threadIdx.x & 63;
    int is64 = g_idx64;
    __shared__ int u_s[32];
    __shared__ float a_s[32 * 8];
    float acc = 0.f;
    for (int s0 = s; s0 < e2; s0 += 32) {
        int cnt = min(32, e2 - s0);
        __syncthreads();
        if ((int)threadIdx.x < cnt) {
            int ee = g_perm[s0 + threadIdx.x];
            u_s[threadIdx.x] = edgeAt(hi, ee, is64);
        }
        if ((int)threadIdx.x < cnt * 8) {
            int j = threadIdx.x >> 3, bb = threadIdx.x & 7;
            a_s[threadIdx.x] = g_alpha[g_perm[s0 + j] * 8 + bb];
        }
        __syncthreads();
        for (int j = 0; j < cnt; j++)
            acc += a_s[j * 8 + b] * g_out1[(u_s[j] * NBAT + b) * NC + c];
    }
    out[((size_t)b * NNODE + n) * NC + c] = acc * (float)(e2 - s);
}

// ---------------- launch ----------------
extern "C" void kernel_launch(void* const* d_in, const int* in_sizes, int n_in,
                              void* d_out, int out_size) {
    const float* x   = (const float*)d_in[0];
    const float* Wq  = (const float*)d_in[1];
    const float* bq  = (const float*)d_in[2];
    const float* Wk  = (const float*)d_in[3];
    const float* bk  = (const float*)d_in[4];
    const float* Wv  = (const float*)d_in[5];
    const float* bv  = (const float*)d_in[6];
    const float* att = (const float*)d_in[7];
    const float* adj = (const float*)d_in[8];
    const int*   hi  = (const int*)d_in[9];
    float* out = (float*)d_out;

    k_detect<<<1, 32>>>(hi);
    k_zero_deg<<<(NNODE + 255) / 256, 256>>>();
    k_hist<<<NE / 256, 256>>>(hi);
    k_scan<<<1, 1024>>>();
    k_scatter<<<NE / 256, 256>>>(hi);

    k_si<<<NNODE, 256>>>(x, att);
    k_agg<<<NU, 512>>>(x, hi);
    k_weff<<<1, 64>>>(Wv, bv, att);
    k_qk<<<dim3(16, 8), 256>>>(Wq, bq, Wk, bk);
    k_vj<<<256, 512>>>();

    size_t attn_smem = (size_t)(32 * 65 + 64 * 65 + 512 + 32 * 512) * sizeof(float);
    cudaFuncSetAttribute(k_attn, cudaFuncAttributeMaxDynamicSharedMemorySize, (int)attn_smem);
    k_attn<<<dim3(16, 8), 256, attn_smem>>>(adj);

    k_alpha_raw<<<NE * NBAT / 256, 256>>>(hi);
    k_nodesm<<<(NNODE * NBAT + 255) / 256, 256>>>();
    k_out1<<<NU, 512>>>(x, hi);
    k_out2<<<NNODE, 512>>>(hi, out);
}

// round 2
// speedup vs baseline: 1.0696x; 1.0696x over previous
#include <cuda_runtime.h>

#define NNODE 20000
#define NU    512
#define NE    81920
#define NBAT  8
#define NC    64
#define SCAN_BS 256
#define NSB   ((NNODE + SCAN_BS - 1) / SCAN_BS)   // 79

// ---------------- device scratch ----------------
__device__ int   g_idx64;
__device__ int   g_deg[NNODE];
__device__ int   g_rowstart[NNODE + 1];
__device__ int   g_cursor[NNODE];
__device__ int   g_bsum[NSB];
__device__ int   g_boff[NSB];
__device__ int   g_perm[NE];
__device__ int   g_pos[NE];
__device__ int   g_edgestart[NU + 1];
__device__ float g_si[NNODE * NBAT];
__device__ float g_sj[NU * NBAT];
__device__ float g_agg[NBAT * NU * NC];       // [b][u][c]
__device__ float g_qt[NBAT * NC * NU];        // [b][c][u]  (transposed)
__device__ float g_kt[NBAT * NC * NU];        // [b][c][u]
__device__ float g_vj[NBAT * NU];
__device__ float g_wv[NC];
__device__ float g_cv;
__device__ float g_alpha_e[NE * NBAT];        // raw alpha, original order
__device__ float g_alpha_p[NE * NBAT];        // raw alpha, node-CSR order
__device__ float g_nmax[NNODE * NBAT];
__device__ float g_ndinv[NNODE * NBAT];
__device__ float g_out1[NU * NBAT * NC];      // [u][b][c]

__device__ __forceinline__ int nodeAt(const int* hi, int e, int is64) {
    return is64 ? hi[2 * e] : hi[e];
}
__device__ __forceinline__ int edgeAt(const int* hi, int e, int is64) {
    return is64 ? hi[2 * (NE + e)] : hi[NE + e];
}

// ---------------- fused setup: idx-detect + zero deg + weff + s_i ----------------
__global__ void k_setup(const int* __restrict__ hi, const float* __restrict__ x,
                        const float* __restrict__ att, const float* __restrict__ Wv,
                        const float* __restrict__ bv) {
    int blk = blockIdx.x;
    if (blk < NSB) {                                   // zero degree histogram
        int i = blk * 256 + threadIdx.x;
        if (i < NNODE) g_deg[i] = 0;
        return;
    }
    if (blk == NSB) {                                  // detect + weff
        int t = threadIdx.x;
        if (t == 0) {
            int odd_or = 0;
            for (int i = 0; i < 64; i++) odd_or |= hi[2 * i + 1];
            g_idx64 = (odd_or == 0) ? 1 : 0;
        }
        if (t < NC) {
            float w = 0.f;
            for (int c = 0; c < NC; c++) w += Wv[c * NC + t] * att[NC + c];
            g_wv[t] = w;
            if (t == 0) {
                float cv = 0.f;
                for (int c = 0; c < NC; c++) cv += bv[c] * att[NC + c];
                g_cv = cv;
            }
        }
        return;
    }
    // s_i: one block per node, 8 warps = 8 batches
    int n = blk - NSB - 1;
    int b = threadIdx.x >> 5;
    int lane = threadIdx.x & 31;
    const float* row = x + ((size_t)b * NNODE + n) * NC;
    float v = row[lane] * att[lane] + row[lane + 32] * att[lane + 32];
    #pragma unroll
    for (int o = 16; o; o >>= 1) v += __shfl_down_sync(0xffffffffu, v, o);
    if (lane == 0) g_si[n * NBAT + b] = v;
}

// ---------------- histogram + hyperedge segment starts ----------------
__global__ void k_hist(const int* __restrict__ hi) {
    int i = blockIdx.x * blockDim.x + threadIdx.x;
    if (i >= NE) return;
    int is64 = g_idx64;
    int n = nodeAt(hi, i, is64);
    atomicAdd(&g_deg[n], 1);
    int u  = edgeAt(hi, i, is64);
    int up = (i == 0) ? -1 : edgeAt(hi, i - 1, is64);
    if (u != up) g_edgestart[u] = i;
    if (i == NE - 1) g_edgestart[NU] = NE;
}

// ---------------- multi-block exclusive scan ----------------
__global__ void k_scan1() {
    __shared__ int wsum[8];
    int tid = threadIdx.x, lane = tid & 31, w = tid >> 5;
    int i = blockIdx.x * SCAN_BS + tid;
    int v = (i < NNODE) ? g_deg[i] : 0;
    int xv = v;
    #pragma unroll
    for (int o = 1; o < 32; o <<= 1) {
        int y = __shfl_up_sync(0xffffffffu, xv, o);
        if (lane >= o) xv += y;
    }
    if (lane == 31) wsum[w] = xv;
    __syncthreads();
    if (w == 0) {
        int t = (lane < 8) ? wsum[lane] : 0;
        #pragma unroll
        for (int o = 1; o < 8; o <<= 1) {
            int y = __shfl_up_sync(0xffffffffu, t, o);
            if (lane >= o) t += y;
        }
        if (lane < 8) wsum[lane] = t;
    }
    __syncthreads();
    int woff = (w == 0) ? 0 : wsum[w - 1];
    if (i < NNODE) g_rowstart[i] = woff + xv - v;
    if (tid == 0) g_bsum[blockIdx.x] = wsum[7];
}

__global__ void k_scan2() {
    __shared__ int wsum[4];
    int tid = threadIdx.x, lane = tid & 31, w = tid >> 5;
    int v = (tid < NSB) ? g_bsum[tid] : 0;
    int xv = v;
    #pragma unroll
    for (int o = 1; o < 32; o <<= 1) {
        int y = __shfl_up_sync(0xffffffffu, xv, o);
        if (lane >= o) xv += y;
    }
    if (lane == 31) wsum[w] = xv;
    __syncthreads();
    if (w == 0) {
        int t = (lane < 4) ? wsum[lane] : 0;
        #pragma unroll
        for (int o = 1; o < 4; o <<= 1) {
            int y = __shfl_up_sync(0xffffffffu, t, o);
            if (lane >= o) t += y;
        }
        if (lane < 4) wsum[lane] = t;
    }
    __syncthreads();
    int woff = (w == 0) ? 0 : wsum[w - 1];
    if (tid < NSB) g_boff[tid] = woff + xv - v;
    if (tid == 0) g_rowstart[NNODE] = NE;
}

__global__ void k_scan3() {
    int i = blockIdx.x * SCAN_BS + threadIdx.x;
    if (i >= NNODE) return;
    int r = g_rowstart[i] + g_boff[blockIdx.x];
    g_rowstart[i] = r;
    g_cursor[i] = r;
}

__global__ void k_scatter(const int* __restrict__ hi) {
    int e = blockIdx.x * blockDim.x + threadIdx.x;
    if (e >= NE) return;
    int n = nodeAt(hi, e, g_idx64);
    int pos = atomicAdd(&g_cursor[n], 1);
    g_perm[pos] = e;
    g_pos[e] = pos;
}

// ---------------- agg[b,u,c] ----------------
__global__ void k_agg(const float* __restrict__ x, const int* __restrict__ hi) {
    int u = blockIdx.x;
    int start = g_edgestart[u], end = g_edgestart[u + 1];
    int b = threadIdx.x >> 6, c = threadIdx.x & 63;
    int is64 = g_idx64;
    __shared__ int nidx[256];
    float acc = 0.f;
    for (int s0 = start; s0 < end; s0 += 256) {
        int cnt = min(256, end - s0);
        __syncthreads();
        if ((int)threadIdx.x < cnt) nidx[threadIdx.x] = nodeAt(hi, s0 + threadIdx.x, is64);
        __syncthreads();
        for (int j = 0; j < cnt; j++)
            acc += x[((size_t)b * NNODE + nidx[j]) * NC + c];
    }
    g_agg[(b * NU + u) * NC + c] = acc;
}

// ---------------- q,k projection (transposed output) + vj ----------------
__global__ void k_qk(const float* __restrict__ Wq, const float* __restrict__ bq,
                     const float* __restrict__ Wk, const float* __restrict__ bk) {
    int b  = blockIdx.y;
    int u0 = blockIdx.x * 32;
    __shared__ float wq_s[64 * 65];
    __shared__ float wk_s[64 * 65];
    __shared__ float agg_s[32 * 65];
    int tid = threadIdx.x;
    for (int i = tid; i < 4096; i += 256) {
        int c = i >> 6, k = i & 63;
        wq_s[c * 65 + k] = Wq[i];
        wk_s[c * 65 + k] = Wk[i];
    }
    for (int i = tid; i < 2048; i += 256) {
        int r = i >> 6, c = i & 63;
        agg_s[r * 65 + c] = g_agg[(b * NU + u0 + r) * NC + c];
    }
    __syncthreads();

    int c = tid & 63, g = tid >> 6;
    float qa[8], ka[8];
    float bqc = bq[c], bkc = bk[c];
    #pragma unroll
    for (int rr = 0; rr < 8; rr++) { qa[rr] = bqc; ka[rr] = bkc; }
    #pragma unroll 8
    for (int k = 0; k < 64; k++) {
        float w1 = wq_s[c * 65 + k];
        float w2 = wk_s[c * 65 + k];
        #pragma unroll
        for (int rr = 0; rr < 8; rr++) {
            float a = agg_s[(g * 8 + rr) * 65 + k];
            qa[rr] += a * w1;
            ka[rr] += a * w2;
        }
    }
    #pragma unroll
    for (int rr = 0; rr < 8; rr++) {
        int u = u0 + g * 8 + rr;
        g_qt[(b * 64 + c) * NU + u] = qa[rr];
        g_kt[(b * 64 + c) * NU + u] = ka[rr];
    }

    // vj = agg . wv + cv for this block's 32 rows
    __syncthreads();
    int w = tid >> 5, lane = tid & 31;
    #pragma unroll
    for (int rr = 0; rr < 4; rr++) {
        int r = w * 4 + rr;
        float v = agg_s[r * 65 + lane] * g_wv[lane] +
                  agg_s[r * 65 + lane + 32] * g_wv[lane + 32];
        #pragma unroll
        for (int o = 16; o; o >>= 1) v += __shfl_down_sync(0xffffffffu, v, o);
        if (lane == 0) g_vj[b * NU + u0 + r] = v + g_cv;
    }
}

// ---------------- masked attention + softmax + vj-dot -> s_j ----------------
__global__ void __launch_bounds__(256, 1) k_attn(const float* __restrict__ adj) {
    extern __shared__ float sm[];
    float* k_s  = sm;                   // 64*512
    float* q_s  = k_s + 64 * 512;       // 64*32
    float* vj_s = q_s + 64 * 32;        // 512
    float* sc   = vj_s + 512;           // 32*512

    int b  = blockIdx.y;
    int u0 = blockIdx.x * 32;
    int tid = threadIdx.x;

    // stage k (full, transposed layout [c][v]) via float4
    const float4* ksrc = (const float4*)(g_kt) + (size_t)b * (64 * NU / 4);
    float4* kdst = (float4*)k_s;
    for (int i = tid; i < 64 * NU / 4; i += 256) kdst[i] = ksrc[i];
    // stage q rows u0..u0+31 (layout [c][u])
    for (int i = tid; i < 64 * 32; i += 256) {
        int c = i >> 5, u = i & 31;
        q_s[c * 32 + u] = g_qt[(b * 64 + c) * NU + u0 + u];
    }
    for (int i = tid; i < 512; i += 256) vj_s[i] = g_vj[b * NU + i];
    __syncthreads();

    int ug = (tid >> 6) * 8;         // 4 groups of 8 rows
    int vg = (tid & 63) * 8;         // 64 groups of 8 cols
    float acc[8][8] = {};
    const float4* k4 = (const float4*)k_s;
    const float4* q4 = (const float4*)q_s;
    int kv_i = vg >> 2, qu_i = ug >> 2;
    #pragma unroll 4
    for (int kk = 0; kk < 64; kk++) {
        float4 kv0 = k4[kk * 128 + kv_i];
        float4 kv1 = k4[kk * 128 + kv_i + 1];
        float4 qv0 = q4[kk * 8 + qu_i];
        float4 qv1 = q4[kk * 8 + qu_i + 1];
        float qa[8] = {qv0.x, qv0.y, qv0.z, qv0.w, qv1.x, qv1.y, qv1.z, qv1.w};
        float kb[8] = {kv0.x, kv0.y, kv0.z, kv0.w, kv1.x, kv1.y, kv1.z, kv1.w};
        #pragma unroll
        for (int i = 0; i < 8; i++)
            #pragma unroll
            for (int j = 0; j < 8; j++)
                acc[i][j] += qa[i] * kb[j];
    }
    // mask + write scores
    #pragma unroll
    for (int i = 0; i < 8; i++) {
        int u = ug + i;
        const float4* arow = (const float4*)(adj + (size_t)(u0 + u) * NU + vg);
        float4 a0 = arow[0], a1 = arow[1];
        float4 s0, s1;
        s0.x = acc[i][0] * 0.125f - (1.f - a0.x) * 500.f;
        s0.y = acc[i][1] * 0.125f - (1.f - a0.y) * 500.f;
        s0.z = acc[i][2] * 0.125f - (1.f - a0.z) * 500.f;
        s0.w = acc[i][3] * 0.125f - (1.f - a0.w) * 500.f;
        s1.x = acc[i][4] * 0.125f - (1.f - a1.x) * 500.f;
        s1.y = acc[i][5] * 0.125f - (1.f - a1.y) * 500.f;
        s1.z = acc[i][6] * 0.125f - (1.f - a1.z) * 500.f;
        s1.w = acc[i][7] * 0.125f - (1.f - a1.w) * 500.f;
        *(float4*)&sc[u * 512 + vg]     = s0;
        *(float4*)&sc[u * 512 + vg + 4] = s1;
    }
    __syncthreads();

    int w = tid >> 5, lane = tid & 31;
    #pragma unroll
    for (int rr = 0; rr < 4; rr++) {
        int u = w * 4 + rr;
        float m = -1e30f;
        for (int v = lane; v < 512; v += 32) m = fmaxf(m, sc[u * 512 + v]);
        #pragma unroll
        for (int o = 16; o; o >>= 1) m = fmaxf(m, __shfl_xor_sync(0xffffffffu, m, o));
        float s = 0.f, d = 0.f;
        for (int v = lane; v < 512; v += 32) {
            float ex = __expf(sc[u * 512 + v] - m);
            s += ex;
            d += ex * vj_s[v];
        }
        #pragma unroll
        for (int o = 16; o; o >>= 1) {
            s += __shfl_xor_sync(0xffffffffu, s, o);
            d += __shfl_xor_sync(0xffffffffu, d, o);
        }
        if (lane == 0) g_sj[(u0 + u) * NBAT + b] = d / s;
    }
}

// ---------------- raw alpha in both layouts ----------------
__global__ void k_alpha_raw(const int* __restrict__ hi) {
    int idx = blockIdx.x * blockDim.x + threadIdx.x;
    int e = idx >> 3, b = idx & 7;
    int is64 = g_idx64;
    int n = nodeAt(hi, e, is64);
    int u = edgeAt(hi, e, is64);
    float a = g_si[n * NBAT + b] + g_sj[u * NBAT + b];
    a = (a > 0.f) ? a : 0.2f * a;
    g_alpha_e[idx] = a;
    g_alpha_p[g_pos[e] * NBAT + b] = a;
}

// ---------------- per-(node,b) max and 1/denom ----------------
__global__ void k_nodemax() {
    int idx = blockIdx.x * blockDim.x + threadIdx.x;
    if (idx >= NNODE * NBAT) return;
    int n = idx >> 3, b = idx & 7;
    int s = g_rowstart[n], e2 = g_rowstart[n + 1];
    float m = -1e30f;
    for (int j = s; j < e2; j++) m = fmaxf(m, g_alpha_p[j * NBAT + b]);
    if (s == e2) { g_nmax[idx] = 0.f; g_ndinv[idx] = 0.f; return; }
    float sum = 0.f;
    for (int j = s; j < e2; j++) sum += __expf(g_alpha_p[j * NBAT + b] - m);
    g_nmax[idx] = m;
    g_ndinv[idx] = 1.0f / (sum + 1e-16f);
}

// ---------------- stage 1: out1[u,b,c] ----------------
__global__ void k_out1(const float* __restrict__ x, const int* __restrict__ hi) {
    int u = blockIdx.x;
    int start = g_edgestart[u], end = g_edgestart[u + 1];
    float bn = (end > start) ? 1.0f / (float)(end - start) : 0.0f;
    int b = threadIdx.x >> 6, c = threadIdx.x & 63;
    int is64 = g_idx64;
    __shared__ int nidx[256];
    __shared__ float a_s[256 * 8];
    float acc = 0.f;
    for (int s0 = start; s0 < end; s0 += 256) {
        int cnt = min(256, end - s0);
        __syncthreads();
        for (int i = threadIdx.x; i < cnt; i += 512) nidx[i] = nodeAt(hi, s0 + i, is64);
        __syncthreads();
        for (int i = threadIdx.x; i < cnt * 8; i += 512) {
            int j = i >> 3, bb = i & 7;
            int nb = nidx[j] * NBAT + bb;
            a_s[i] = __expf(g_alpha_e[(s0 + j) * NBAT + bb] - g_nmax[nb]) * g_ndinv[nb];
        }
        __syncthreads();
        for (int j = 0; j < cnt; j++)
            acc += a_s[j * 8 + b] * x[((size_t)b * NNODE + nidx[j]) * NC + c];
    }
    g_out1[(u * NBAT + b) * NC + c] = acc * bn;
}

// ---------------- stage 2: out[b,n,c] ----------------
__global__ void k_out2(const int* __restrict__ hi, float* __restrict__ out) {
    int n = blockIdx.x;
    int s = g_rowstart[n], e2 = g_rowstart[n + 1];
    int b = threadIdx.x >> 6, c = threadIdx.x & 63;
    int is64 = g_idx64;
    __shared__ int u_s[32];
    __shared__ float a_s[32 * 8];
    __shared__ float nm[8], dv[8];
    if (threadIdx.x < 8) {
        nm[threadIdx.x] = g_nmax[n * NBAT + threadIdx.x];
        dv[threadIdx.x] = g_ndinv[n * NBAT + threadIdx.x];
    }
    float acc = 0.f;
    for (int s0 = s; s0 < e2; s0 += 32) {
        int cnt = min(32, e2 - s0);
        __syncthreads();
        if ((int)threadIdx.x < cnt) {
            int ee = g_perm[s0 + threadIdx.x];
            u_s[threadIdx.x] = edgeAt(hi, ee, is64);
        }
        if ((int)threadIdx.x < cnt * 8) {
            int j = threadIdx.x >> 3, bb = threadIdx.x & 7;
            a_s[threadIdx.x] =
                __expf(g_alpha_p[(s0 + j) * NBAT + bb] - nm[bb]) * dv[bb];
        }
        __syncthreads();
        for (int j = 0; j < cnt; j++)
            acc += a_s[j * 8 + b] * g_out1[(u_s[j] * NBAT + b) * NC + c];
    }
    out[((size_t)b * NNODE + n) * NC + c] = acc * (float)(e2 - s);
}

// ---------------- launch ----------------
extern "C" void kernel_launch(void* const* d_in, const int* in_sizes, int n_in,
                              void* d_out, int out_size) {
    const float* x   = (const float*)d_in[0];
    const float* Wq  = (const float*)d_in[1];
    const float* bq  = (const float*)d_in[2];
    const float* Wk  = (const float*)d_in[3];
    const float* bk  = (const float*)d_in[4];
    const float* Wv  = (const float*)d_in[5];
    const float* bv  = (const float*)d_in[6];
    const float* att = (const float*)d_in[7];
    const float* adj = (const float*)d_in[8];
    const int*   hi  = (const int*)d_in[9];
    float* out = (float*)d_out;

    k_setup<<<NSB + 1 + NNODE, 256>>>(hi, x, att, Wv, bv);
    k_hist<<<NE / 256, 256>>>(hi);
    k_scan1<<<NSB, SCAN_BS>>>();
    k_scan2<<<1, 128>>>();
    k_scan3<<<NSB, SCAN_BS>>>();
    k_scatter<<<NE / 256, 256>>>(hi);

    k_agg<<<NU, 512>>>(x, hi);
    k_qk<<<dim3(16, 8), 256>>>(Wq, bq, Wk, bk);

    size_t attn_smem = (size_t)(64 * 512 + 64 * 32 + 512 + 32 * 512) * sizeof(float);
    cudaFuncSetAttribute(k_attn, cudaFuncAttributeMaxDynamicSharedMemorySize, (int)attn_smem);
    k_attn<<<dim3(16, 8), 256, attn_smem>>>(adj);

    k_alpha_raw<<<NE * NBAT / 256, 256>>>(hi);
    k_nodemax<<<(NNODE * NBAT + 255) / 256, 256>>>();
    k_out1<<<NU, 512>>>(x, hi);
    k_out2<<<NNODE, 512>>>(hi, out);
}

// round 3
// speedup vs baseline: 1.8033x; 1.6859x over previous
#include <cuda_runtime.h>

#define NNODE 20000
#define NU    512
#define NE    81920
#define NBAT  8
#define NC    64
#define SCAN_BS 256
#define NSB   ((NNODE + SCAN_BS - 1) / SCAN_BS)   // 79

// ---------------- device scratch ----------------
__device__ int   g_idx64;
__device__ int   g_deg[NNODE];
__device__ int   g_rowstart[NNODE + 1];
__device__ int   g_cursor[NNODE];
__device__ int   g_bsum[NSB];
__device__ int   g_boff[NSB];
__device__ unsigned g_scan_ctr;
__device__ int   g_perm[NE];
__device__ int   g_edgestart[NU + 1];
__device__ float g_si[NNODE * NBAT];
__device__ float g_sj[NU * NBAT];
__device__ float g_qt[NBAT * NC * NU];        // [b][c][u]
__device__ float g_kt[NBAT * NC * NU];        // [b][c][u]
__device__ float g_vj[NBAT * NU];
__device__ float g_wv[NC];
__device__ float g_cv;
__device__ float g_alpha_e[NE * NBAT];        // normalized alpha, original order
__device__ float g_alpha_p[NE * NBAT];        // normalized alpha, node-CSR order
__device__ float g_out1[NU * NBAT * NC];      // [u][b][c]

__device__ __forceinline__ int nodeAt(const int* hi, int e, int is64) {
    return is64 ? hi[2 * e] : hi[e];
}
__device__ __forceinline__ int edgeAt(const int* hi, int e, int is64) {
    return is64 ? hi[2 * (NE + e)] : hi[NE + e];
}

#define SI_BLOCKS ((NNODE * NBAT + 255) / 256)   // 625

// ---------------- fused setup: zero deg + detect + weff + s_i ----------------
__global__ void k_setup(const int* __restrict__ hi, const float* __restrict__ x,
                        const float* __restrict__ att, const float* __restrict__ Wv,
                        const float* __restrict__ bv) {
    int blk = blockIdx.x;
    if (blk < NSB) {
        int i = blk * 256 + threadIdx.x;
        if (i < NNODE) g_deg[i] = 0;
        return;
    }
    if (blk == NSB) {
        int t = threadIdx.x;
        if (t == 0) {
            int odd_or = 0;
            for (int i = 0; i < 64; i++) odd_or |= hi[2 * i + 1];
            g_idx64 = (odd_or == 0) ? 1 : 0;
            g_scan_ctr = 0;
        }
        if (t < NC) {
            float w = 0.f;
            for (int c = 0; c < NC; c++) w += Wv[c * NC + t] * att[NC + c];
            g_wv[t] = w;
            if (t == 0) {
                float cv = 0.f;
                for (int c = 0; c < NC; c++) cv += bv[c] * att[NC + c];
                g_cv = cv;
            }
        }
        return;
    }
    // s_i: one thread per (b,n), idx = b*NNODE + n
    int idx = (blk - NSB - 1) * 256 + threadIdx.x;
    if (idx >= NNODE * NBAT) return;
    int b = idx / NNODE;
    int n = idx - b * NNODE;
    const float4* x4 = (const float4*)x + (size_t)idx * 16;
    const float4* a4 = (const float4*)att;
    float v = 0.f;
    #pragma unroll
    for (int i = 0; i < 16; i++) {
        float4 xv = x4[i], av = a4[i];
        v += xv.x * av.x + xv.y * av.y + xv.z * av.z + xv.w * av.w;
    }
    g_si[n * NBAT + b] = v;
}

// ---------------- histogram + hyperedge segment starts ----------------
__global__ void k_hist(const int* __restrict__ hi) {
    int i = blockIdx.x * blockDim.x + threadIdx.x;
    if (i >= NE) return;
    int is64 = g_idx64;
    int n = nodeAt(hi, i, is64);
    atomicAdd(&g_deg[n], 1);
    int u  = edgeAt(hi, i, is64);
    int up = (i == 0) ? -1 : edgeAt(hi, i - 1, is64);
    if (u != up) g_edgestart[u] = i;
    if (i == NE - 1) g_edgestart[NU] = NE;
}

// ---------------- scan (block partials + fused last-block top scan) ----------------
__global__ void k_scan12() {
    __shared__ int wsum[8];
    __shared__ int isLast;
    int tid = threadIdx.x, lane = tid & 31, w = tid >> 5;
    int i = blockIdx.x * SCAN_BS + tid;
    int v = (i < NNODE) ? g_deg[i] : 0;
    int xv = v;
    #pragma unroll
    for (int o = 1; o < 32; o <<= 1) {
        int y = __shfl_up_sync(0xffffffffu, xv, o);
        if (lane >= o) xv += y;
    }
    if (lane == 31) wsum[w] = xv;
    __syncthreads();
    if (w == 0) {
        int t = (lane < 8) ? wsum[lane] : 0;
        #pragma unroll
        for (int o = 1; o < 8; o <<= 1) {
            int y = __shfl_up_sync(0xffffffffu, t, o);
            if (lane >= o) t += y;
        }
        if (lane < 8) wsum[lane] = t;
    }
    __syncthreads();
    int woff = (w == 0) ? 0 : wsum[w - 1];
    if (i < NNODE) g_rowstart[i] = woff + xv - v;
    if (tid == 0) g_bsum[blockIdx.x] = wsum[7];
    __threadfence();
    if (tid == 0) {
        unsigned d = atomicAdd(&g_scan_ctr, 1u);
        isLast = (d == NSB - 1) ? 1 : 0;
    }
    __syncthreads();
    if (!isLast) return;
    // scan the NSB block sums
    int v2 = (tid < NSB) ? g_bsum[tid] : 0;
    int xv2 = v2;
    #pragma unroll
    for (int o = 1; o < 32; o <<= 1) {
        int y = __shfl_up_sync(0xffffffffu, xv2, o);
        if (lane >= o) xv2 += y;
    }
    __syncthreads();
    if (lane == 31) wsum[w] = xv2;
    __syncthreads();
    if (w == 0) {
        int t = (lane < 8) ? wsum[lane] : 0;
        #pragma unroll
        for (int o = 1; o < 8; o <<= 1) {
            int y = __shfl_up_sync(0xffffffffu, t, o);
            if (lane >= o) t += y;
        }
        if (lane < 8) wsum[lane] = t;
    }
    __syncthreads();
    int woff2 = (w == 0) ? 0 : wsum[w - 1];
    if (tid < NSB) g_boff[tid] = woff2 + xv2 - v2;
}

__global__ void k_scan3() {
    int i = blockIdx.x * SCAN_BS + threadIdx.x;
    if (i == 0) g_rowstart[NNODE] = NE;
    if (i >= NNODE) return;
    int r = g_rowstart[i] + g_boff[blockIdx.x];
    g_rowstart[i] = r;
    g_cursor[i] = r;
}

__global__ void k_scatter(const int* __restrict__ hi) {
    int e = blockIdx.x * blockDim.x + threadIdx.x;
    if (e >= NE) return;
    int n = nodeAt(hi, e, g_idx64);
    int pos = atomicAdd(&g_cursor[n], 1);
    g_perm[pos] = e;
}

// ---------------- fused agg + q/k projection + vj : one block per u ----------------
__global__ void __launch_bounds__(512, 2) k_aggqk(
        const float* __restrict__ x, const int* __restrict__ hi,
        const float* __restrict__ Wq, const float* __restrict__ bq,
        const float* __restrict__ Wk, const float* __restrict__ bk) {
    __shared__ int   nidx[256];
    __shared__ float4 part[4][128];
    __shared__ float wq_s[64 * 65];
    __shared__ float wk_s[64 * 65];
    __shared__ float agg_s[8][65];
    __shared__ float wv_s[64];

    int u = blockIdx.x;
    int tid = threadIdx.x;
    int start = g_edgestart[u], end = g_edgestart[u + 1];
    int is64 = g_idx64;

    for (int i = tid; i < 4096; i += 512) {
        int c = i >> 6, k = i & 63;
        wq_s[c * 65 + k] = Wq[i];
        wk_s[c * 65 + k] = Wk[i];
    }
    if (tid < 64) wv_s[tid] = g_wv[tid];

    int js = tid >> 7;
    int b  = (tid >> 4) & 7;
    int c4 = tid & 15;
    const float4* x4 = (const float4*)x;
    float4 acc = make_float4(0.f, 0.f, 0.f, 0.f);
    for (int s0 = start; s0 < end; s0 += 256) {
        int cnt = min(256, end - s0);
        __syncthreads();
        if (tid < cnt) nidx[tid] = nodeAt(hi, s0 + tid, is64);
        __syncthreads();
        #pragma unroll 4
        for (int j = js; j < cnt; j += 4) {
            float4 xv = x4[((size_t)b * NNODE + nidx[j]) * 16 + c4];
            acc.x += xv.x; acc.y += xv.y; acc.z += xv.z; acc.w += xv.w;
        }
    }
    part[js][b * 16 + c4] = acc;
    __syncthreads();
    if (tid < 128) {
        float4 p0 = part[0][tid], p1 = part[1][tid], p2 = part[2][tid], p3 = part[3][tid];
        float4 r;
        r.x = p0.x + p1.x + p2.x + p3.x;
        r.y = p0.y + p1.y + p2.y + p3.y;
        r.z = p0.z + p1.z + p2.z + p3.z;
        r.w = p0.w + p1.w + p2.w + p3.w;
        int bb = tid >> 4, cc = (tid & 15) * 4;
        agg_s[bb][cc + 0] = r.x;
        agg_s[bb][cc + 1] = r.y;
        agg_s[bb][cc + 2] = r.z;
        agg_s[bb][cc + 3] = r.w;
    }
    __syncthreads();

    // q,k: thread (b2,c) over all 512
    int c = tid & 63, b2 = tid >> 6;
    float qa = bq[c], ka = bk[c];
    #pragma unroll 8
    for (int k = 0; k < 64; k++) {
        float a = agg_s[b2][k];
        qa += a * wq_s[c * 65 + k];
        ka += a * wk_s[c * 65 + k];
    }
    g_qt[(b2 * 64 + c) * NU + u] = qa;
    g_kt[(b2 * 64 + c) * NU + u] = ka;

    // vj: warps 0..7 handle b = warp
    int w = tid >> 5, lane = tid & 31;
    if (w < 8) {
        float v = agg_s[w][lane] * wv_s[lane] + agg_s[w][lane + 32] * wv_s[lane + 32];
        #pragma unroll
        for (int o = 16; o; o >>= 1) v += __shfl_down_sync(0xffffffffu, v, o);
        if (lane == 0) g_vj[w * NU + u] = v + g_cv;
    }
}

// ---------------- masked attention + register softmax -> s_j ----------------
__global__ void __launch_bounds__(256, 1) k_attn(const float* __restrict__ adj) {
    extern __shared__ float sm[];
    float* k_s  = sm;                   // 64*512
    float* q_s  = k_s + 64 * 512;       // 64*32
    float* vj_s = q_s + 64 * 32;        // 512
    __shared__ float redm[8][8];        // [warp][row]
    __shared__ float reds[8][8];
    __shared__ float redd[8][8];

    int b  = blockIdx.y;
    int u0 = blockIdx.x * 32;
    int tid = threadIdx.x;

    const float4* ksrc = (const float4*)(g_kt) + (size_t)b * (64 * NU / 4);
    float4* kdst = (float4*)k_s;
    for (int i = tid; i < 64 * NU / 4; i += 256) kdst[i] = ksrc[i];
    for (int i = tid; i < 64 * 32; i += 256) {
        int c = i >> 5, u = i & 31;
        q_s[c * 32 + u] = g_qt[(b * 64 + c) * NU + u0 + u];
    }
    for (int i = tid; i < 512; i += 256) vj_s[i] = g_vj[b * NU + i];
    __syncthreads();

    int g  = tid >> 6;              // row group: rows g*8..g*8+7
    int ug = g * 8;
    int vg = (tid & 63) * 8;        // cols vg..vg+7
    float acc[8][8] = {};
    const float4* k4 = (const float4*)k_s;
    const float4* q4 = (const float4*)q_s;
    int kv_i = vg >> 2, qu_i = ug >> 2;
    #pragma unroll 4
    for (int kk = 0; kk < 64; kk++) {
        float4 kv0 = k4[kk * 128 + kv_i];
        float4 kv1 = k4[kk * 128 + kv_i + 1];
        float4 qv0 = q4[kk * 8 + qu_i];
        float4 qv1 = q4[kk * 8 + qu_i + 1];
        float qa[8] = {qv0.x, qv0.y, qv0.z, qv0.w, qv1.x, qv1.y, qv1.z, qv1.w};
        float kb[8] = {kv0.x, kv0.y, kv0.z, kv0.w, kv1.x, kv1.y, kv1.z, kv1.w};
        #pragma unroll
        for (int i = 0; i < 8; i++)
            #pragma unroll
            for (int j = 0; j < 8; j++)
                acc[i][j] += qa[i] * kb[j];
    }
    // mask
    float rm[8];
    #pragma unroll
    for (int i = 0; i < 8; i++) {
        int u = ug + i;
        const float4* arow = (const float4*)(adj + (size_t)(u0 + u) * NU + vg);
        float4 a0 = arow[0], a1 = arow[1];
        acc[i][0] = acc[i][0] * 0.125f - (1.f - a0.x) * 500.f;
        acc[i][1] = acc[i][1] * 0.125f - (1.f - a0.y) * 500.f;
        acc[i][2] = acc[i][2] * 0.125f - (1.f - a0.z) * 500.f;
        acc[i][3] = acc[i][3] * 0.125f - (1.f - a0.w) * 500.f;
        acc[i][4] = acc[i][4] * 0.125f - (1.f - a1.x) * 500.f;
        acc[i][5] = acc[i][5] * 0.125f - (1.f - a1.y) * 500.f;
        acc[i][6] = acc[i][6] * 0.125f - (1.f - a1.z) * 500.f;
        acc[i][7] = acc[i][7] * 0.125f - (1.f - a1.w) * 500.f;
        float m = acc[i][0];
        #pragma unroll
        for (int j = 1; j < 8; j++) m = fmaxf(m, acc[i][j]);
        rm[i] = m;
    }
    int w = tid >> 5, lane = tid & 31;
    // cross-thread max over the 64 threads (2 warps) of this row group
    #pragma unroll
    for (int i = 0; i < 8; i++) {
        float m = rm[i];
        #pragma unroll
        for (int o = 16; o; o >>= 1) m = fmaxf(m, __shfl_xor_sync(0xffffffffu, m, o));
        if (lane == 0) redm[w][i] = m;
    }
    __syncthreads();
    #pragma unroll
    for (int i = 0; i < 8; i++) rm[i] = fmaxf(redm[g * 2][i], redm[g * 2 + 1][i]);

    float vjv[8];
    {
        const float4* v4 = (const float4*)(vj_s + vg);
        float4 v0 = v4[0], v1 = v4[1];
        vjv[0] = v0.x; vjv[1] = v0.y; vjv[2] = v0.z; vjv[3] = v0.w;
        vjv[4] = v1.x; vjv[5] = v1.y; vjv[6] = v1.z; vjv[7] = v1.w;
    }
    #pragma unroll
    for (int i = 0; i < 8; i++) {
        float s = 0.f, d = 0.f;
        #pragma unroll
        for (int j = 0; j < 8; j++) {
            float e = __expf(acc[i][j] - rm[i]);
            s += e;
            d += e * vjv[j];
        }
        #pragma unroll
        for (int o = 16; o; o >>= 1) {
            s += __shfl_xor_sync(0xffffffffu, s, o);
            d += __shfl_xor_sync(0xffffffffu, d, o);
        }
        if (lane == 0) { reds[w][i] = s; redd[w][i] = d; }
    }
    __syncthreads();
    if ((tid & 63) < 8) {
        int i = tid & 63;
        float s = reds[g * 2][i] + reds[g * 2 + 1][i];
        float d = redd[g * 2][i] + redd[g * 2 + 1][i];
        g_sj[(u0 + ug + i) * NBAT + b] = d / s;
    }
}

// ---------------- fused alpha + node softmax (writes normalized, both layouts) ----------------
__global__ void k_nodealpha(const int* __restrict__ hi) {
    int idx = blockIdx.x * blockDim.x + threadIdx.x;
    if (idx >= NNODE * NBAT) return;
    int n = idx >> 3, b = idx & 7;
    int s = g_rowstart[n], e2 = g_rowstart[n + 1];
    if (s == e2) return;
    int is64 = g_idx64;
    float si = g_si[n * NBAT + b];
    float m = -1e30f;
    for (int j = s; j < e2; j++) {
        int e = g_perm[j];
        int u = edgeAt(hi, e, is64);
        float a = si + g_sj[u * NBAT + b];
        a = (a > 0.f) ? a : 0.2f * a;
        g_alpha_p[j * NBAT + b] = a;
        m = fmaxf(m, a);
    }
    float sum = 0.f;
    for (int j = s; j < e2; j++) sum += __expf(g_alpha_p[j * NBAT + b] - m);
    float inv = 1.0f / (sum + 1e-16f);
    for (int j = s; j < e2; j++) {
        float v = __expf(g_alpha_p[j * NBAT + b] - m) * inv;
        g_alpha_p[j * NBAT + b] = v;
        g_alpha_e[g_perm[j] * NBAT + b] = v;
    }
}

// ---------------- stage 1: out1[u,b,c] ----------------
__global__ void __launch_bounds__(512, 2) k_out1(const float* __restrict__ x,
                                                 const int* __restrict__ hi) {
    __shared__ int   nidx[256];
    __shared__ float a_s[256 * 8];
    __shared__ float4 part[4][128];
    int u = blockIdx.x;
    int tid = threadIdx.x;
    int start = g_edgestart[u], end = g_edgestart[u + 1];
    float bn = (end > start) ? 1.0f / (float)(end - start) : 0.0f;
    int is64 = g_idx64;

    int js = tid >> 7;
    int b  = (tid >> 4) & 7;
    int c4 = tid & 15;
    const float4* x4 = (const float4*)x;
    float4 acc = make_float4(0.f, 0.f, 0.f, 0.f);
    for (int s0 = start; s0 < end; s0 += 256) {
        int cnt = min(256, end - s0);
        __syncthreads();
        if (tid < cnt) nidx[tid] = nodeAt(hi, s0 + tid, is64);
        for (int i = tid; i < cnt * 8; i += 512) a_s[i] = g_alpha_e[s0 * 8 + i];
        __syncthreads();
        #pragma unroll 4
        for (int j = js; j < cnt; j += 4) {
            float a = a_s[j * 8 + b];
            float4 xv = x4[((size_t)b * NNODE + nidx[j]) * 16 + c4];
            acc.x += a * xv.x; acc.y += a * xv.y; acc.z += a * xv.z; acc.w += a * xv.w;
        }
    }
    part[js][b * 16 + c4] = acc;
    __syncthreads();
    if (tid < 128) {
        float4 p0 = part[0][tid], p1 = part[1][tid], p2 = part[2][tid], p3 = part[3][tid];
        float4 r;
        r.x = (p0.x + p1.x + p2.x + p3.x) * bn;
        r.y = (p0.y + p1.y + p2.y + p3.y) * bn;
        r.z = (p0.z + p1.z + p2.z + p3.z) * bn;
        r.w = (p0.w + p1.w + p2.w + p3.w) * bn;
        int bb = tid >> 4, cc = tid & 15;
        ((float4*)g_out1)[(u * 8 + bb) * 16 + cc] = r;
    }
}

// ---------------- stage 2: flat, thread per (n,b,c4) ----------------
__global__ void k_out2(const int* __restrict__ hi, float* __restrict__ out) {
    int idx = blockIdx.x * blockDim.x + threadIdx.x;   // NNODE*128
    int n  = idx >> 7;
    int b  = (idx >> 4) & 7;
    int c4 = idx & 15;
    if (n >= NNODE) return;
    int s = g_rowstart[n], e2 = g_rowstart[n + 1];
    int is64 = g_idx64;
    const float4* o4 = (const float4*)g_out1;
    float4 acc = make_float4(0.f, 0.f, 0.f, 0.f);
    for (int j = s; j < e2; j++) {
        int e = g_perm[j];
        int u = edgeAt(hi, e, is64);
        float a = g_alpha_p[j * NBAT + b];
        float4 ov = o4[(u * 8 + b) * 16 + c4];
        acc.x += a * ov.x; acc.y += a * ov.y; acc.z += a * ov.z; acc.w += a * ov.w;
    }
    float D = (float)(e2 - s);
    acc.x *= D; acc.y *= D; acc.z *= D; acc.w *= D;
    ((float4*)out)[((size_t)b * NNODE + n) * 16 + c4] = acc;
}

// ---------------- launch ----------------
extern "C" void kernel_launch(void* const* d_in, const int* in_sizes, int n_in,
                              void* d_out, int out_size) {
    const float* x   = (const float*)d_in[0];
    const float* Wq  = (const float*)d_in[1];
    const float* bq  = (const float*)d_in[2];
    const float* Wk  = (const float*)d_in[3];
    const float* bk  = (const float*)d_in[4];
    const float* Wv  = (const float*)d_in[5];
    const float* bv  = (const float*)d_in[6];
    const float* att = (const float*)d_in[7];
    const float* adj = (const float*)d_in[8];
    const int*   hi  = (const int*)d_in[9];
    float* out = (float*)d_out;

    k_setup<<<NSB + 1 + SI_BLOCKS, 256>>>(hi, x, att, Wv, bv);
    k_hist<<<NE / 256, 256>>>(hi);
    k_scan12<<<NSB, SCAN_BS>>>();
    k_scan3<<<NSB, SCAN_BS>>>();
    k_scatter<<<NE / 256, 256>>>(hi);

    k_aggqk<<<NU, 512>>>(x, hi, Wq, bq, Wk, bk);

    size_t attn_smem = (size_t)(64 * 512 + 64 * 32 + 512) * sizeof(float);
    cudaFuncSetAttribute(k_attn, cudaFuncAttributeMaxDynamicSharedMemorySize, (int)attn_smem);
    k_attn<<<dim3(16, 8), 256, attn_smem>>>(adj);

    k_nodealpha<<<(NNODE * NBAT + 255) / 256, 256>>>(hi);
    k_out1<<<NU, 512>>>(x, hi);
    k_out2<<<(NNODE * 128 + 255) / 256, 256>>>(hi, out);
}

// round 4
// speedup vs baseline: 1.8668x; 1.0352x over previous
#include <cuda_runtime.h>

#define NNODE 20000
#define NU    512
#define NE    81920
#define NBAT  8
#define NC    64
#define SCAN_BS 256
#define NSB   ((NNODE + SCAN_BS - 1) / SCAN_BS)   // 79

// ---------------- device scratch ----------------
__device__ int   g_idx64;
__device__ int   g_deg[NNODE];
__device__ int   g_rowstart[NNODE + 1];
__device__ int   g_cursor[NNODE];
__device__ int   g_bsum[NSB];
__device__ int   g_boff[NSB];
__device__ unsigned g_scan_ctr;
__device__ int   g_perm[NE];
__device__ int   g_uperm[NE];
__device__ float g_si[NNODE * NBAT];
__device__ float g_sj[NU * NBAT];
__device__ float g_qt[NBAT * NC * NU];        // [b][c][u]
__device__ float g_kt[NBAT * NC * NU];        // [b][c][u]
__device__ float g_vj[NBAT * NU];
__device__ float g_wv[NC];
__device__ float g_cv;
__device__ float g_alpha_e[NE * NBAT];
__device__ float g_alpha_p[NE * NBAT];
__device__ float g_out1[NU * NBAT * NC];      // [u][b][c]

__device__ __forceinline__ int nodeAt(const int* hi, int e, int is64) {
    return is64 ? hi[2 * e] : hi[e];
}
__device__ __forceinline__ int edgeAt(const int* hi, int e, int is64) {
    return is64 ? hi[2 * (NE + e)] : hi[NE + e];
}
__device__ __forceinline__ int edgeLB(const int* hi, int target, int is64) {
    int lo = 0, hi_ = NE;
    while (lo < hi_) {
        int mid = (lo + hi_) >> 1;
        if (edgeAt(hi, mid, is64) < target) lo = mid + 1; else hi_ = mid;
    }
    return lo;
}

__global__ void k_init(const int* __restrict__ hi, const float* __restrict__ att,
                       const float* __restrict__ Wv, const float* __restrict__ bv) {
    int t = threadIdx.x;
    if (t == 0) {
        int odd_or = 0;
        for (int i = 0; i < 64; i++) odd_or |= hi[2 * i + 1];
        g_idx64 = (odd_or == 0) ? 1 : 0;
        g_scan_ctr = 0;
    }
    if (t < NC) {
        float w = 0.f;
        for (int c = 0; c < NC; c++) w += Wv[c * NC + t] * att[NC + c];
        g_wv[t] = w;
        if (t == 0) {
            float cv = 0.f;
            for (int c = 0; c < NC; c++) cv += bv[c] * att[NC + c];
            g_cv = cv;
        }
    }
}

__global__ void k_zero() {
    int i = blockIdx.x * blockDim.x + threadIdx.x;
    if (i < NNODE) g_deg[i] = 0;
}

__global__ void k_hist(const int* __restrict__ hi) {
    int i = blockIdx.x * blockDim.x + threadIdx.x;
    if (i >= NE) return;
    atomicAdd(&g_deg[nodeAt(hi, i, g_idx64)], 1);
}

__global__ void k_scan12() {
    __shared__ int wsum[8];
    __shared__ int isLast;
    int tid = threadIdx.x, lane = tid & 31, w = tid >> 5;
    int i = blockIdx.x * SCAN_BS + tid;
    int v = (i < NNODE) ? g_deg[i] : 0;
    int xv = v;
    #pragma unroll
    for (int o = 1; o < 32; o <<= 1) {
        int y = __shfl_up_sync(0xffffffffu, xv, o);
        if (lane >= o) xv += y;
    }
    if (lane == 31) wsum[w] = xv;
    __syncthreads();
    if (w == 0) {
        int t = (lane < 8) ? wsum[lane] : 0;
        #pragma unroll
        for (int o = 1; o < 8; o <<= 1) {
            int y = __shfl_up_sync(0xffffffffu, t, o);
            if (lane >= o) t += y;
        }
        if (lane < 8) wsum[lane] = t;
    }
    __syncthreads();
    int woff = (w == 0) ? 0 : wsum[w - 1];
    if (i < NNODE) g_rowstart[i] = woff + xv - v;
    if (tid == 0) g_bsum[blockIdx.x] = wsum[7];
    __threadfence();
    if (tid == 0) {
        unsigned d = atomicAdd(&g_scan_ctr, 1u);
        isLast = (d == NSB - 1) ? 1 : 0;
    }
    __syncthreads();
    if (!isLast) return;
    int v2 = (tid < NSB) ? g_bsum[tid] : 0;
    int xv2 = v2;
    #pragma unroll
    for (int o = 1; o < 32; o <<= 1) {
        int y = __shfl_up_sync(0xffffffffu, xv2, o);
        if (lane >= o) xv2 += y;
    }
    __syncthreads();
    if (lane == 31) wsum[w] = xv2;
    __syncthreads();
    if (w == 0) {
        int t = (lane < 8) ? wsum[lane] : 0;
        #pragma unroll
        for (int o = 1; o < 8; o <<= 1) {
            int y = __shfl_up_sync(0xffffffffu, t, o);
            if (lane >= o) t += y;
        }
        if (lane < 8) wsum[lane] = t;
    }
    __syncthreads();
    int woff2 = (w == 0) ? 0 : wsum[w - 1];
    if (tid < NSB) g_boff[tid] = woff2 + xv2 - v2;
}

__global__ void k_scan3() {
    int i = blockIdx.x * SCAN_BS + threadIdx.x;
    if (i == 0) g_rowstart[NNODE] = NE;
    if (i >= NNODE) return;
    int r = g_rowstart[i] + g_boff[blockIdx.x];
    g_rowstart[i] = r;
    g_cursor[i] = r;
}

__global__ void k_scatter(const int* __restrict__ hi) {
    int e = blockIdx.x * blockDim.x + threadIdx.x;
    if (e >= NE) return;
    int is64 = g_idx64;
    int n = nodeAt(hi, e, is64);
    int pos = atomicAdd(&g_cursor[n], 1);
    g_perm[pos] = e;
    g_uperm[pos] = edgeAt(hi, e, is64);
}

__global__ void k_si(const float* __restrict__ x, const float* __restrict__ att) {
    int idx = blockIdx.x * blockDim.x + threadIdx.x;
    if (idx >= NNODE * NBAT) return;
    int b = idx / NNODE;
    int n = idx - b * NNODE;
    const float4* x4 = (const float4*)x + (size_t)idx * 16;
    const float4* a4 = (const float4*)att;
    float v = 0.f;
    #pragma unroll
    for (int i = 0; i < 16; i++) {
        float4 xv = x4[i], av = a4[i];
        v += xv.x * av.x + xv.y * av.y + xv.z * av.z + xv.w * av.w;
    }
    g_si[n * NBAT + b] = v;
}

__global__ void __launch_bounds__(512, 2) k_aggqk(
        const float* __restrict__ x, const int* __restrict__ hi,
        const float* __restrict__ Wq, const float* __restrict__ bq,
        const float* __restrict__ Wk, const float* __restrict__ bk) {
    __shared__ int   nidx[256];
    __shared__ int   sb[2];
    __shared__ float4 part[4][128];
    __shared__ float wq_s[64 * 65];
    __shared__ float wk_s[64 * 65];
    __shared__ float agg_s[8][65];
    __shared__ float wv_s[64];

    int u = blockIdx.x;
    int tid = threadIdx.x;
    int is64 = g_idx64;
    if (tid < 2) sb[tid] = edgeLB(hi, u + tid, is64);

    for (int i = tid; i < 4096; i += 512) {
        int c = i >> 6, k = i & 63;
        wq_s[c * 65 + k] = Wq[i];
        wk_s[c * 65 + k] = Wk[i];
    }
    if (tid < 64) wv_s[tid] = g_wv[tid];
    __syncthreads();
    int start = sb[0], end = sb[1];

    int js = tid >> 7;
    int b  = (tid >> 4) & 7;
    int c4 = tid & 15;
    const float4* x4 = (const float4*)x;
    float4 acc = make_float4(0.f, 0.f, 0.f, 0.f);
    for (int s0 = start; s0 < end; s0 += 256) {
        int cnt = min(256, end - s0);
        __syncthreads();
        if (tid < cnt) nidx[tid] = nodeAt(hi, s0 + tid, is64);
        __syncthreads();
        #pragma unroll 4
        for (int j = js; j < cnt; j += 4) {
            float4 xv = x4[((size_t)b * NNODE + nidx[j]) * 16 + c4];
            acc.x += xv.x; acc.y += xv.y; acc.z += xv.z; acc.w += xv.w;
        }
    }
    part[js][b * 16 + c4] = acc;
    __syncthreads();
    if (tid < 128) {
        float4 p0 = part[0][tid], p1 = part[1][tid], p2 = part[2][tid], p3 = part[3][tid];
        float4 r;
        r.x = p0.x + p1.x + p2.x + p3.x;
        r.y = p0.y + p1.y + p2.y + p3.y;
        r.z = p0.z + p1.z + p2.z + p3.z;
        r.w = p0.w + p1.w + p2.w + p3.w;
        int bb = tid >> 4, cc = (tid & 15) * 4;
        agg_s[bb][cc + 0] = r.x;
        agg_s[bb][cc + 1] = r.y;
        agg_s[bb][cc + 2] = r.z;
        agg_s[bb][cc + 3] = r.w;
    }
    __syncthreads();

    int c = tid & 63, b2 = tid >> 6;
    float qa = bq[c], ka = bk[c];
    #pragma unroll 8
    for (int k = 0; k < 64; k++) {
        float a = agg_s[b2][k];
        qa += a * wq_s[c * 65 + k];
        ka += a * wk_s[c * 65 + k];
    }
    g_qt[(b2 * 64 + c) * NU + u] = qa;
    g_kt[(b2 * 64 + c) * NU + u] = ka;

    int w = tid >> 5, lane = tid & 31;
    if (w < 8) {
        float v = agg_s[w][lane] * wv_s[lane] + agg_s[w][lane + 32] * wv_s[lane + 32];
        #pragma unroll
        for (int o = 16; o; o >>= 1) v += __shfl_down_sync(0xffffffffu, v, o);
        if (lane == 0) g_vj[w * NU + u] = v + g_cv;
    }
}

__global__ void __launch_bounds__(256, 1) k_attn(const float* __restrict__ adj) {
    extern __shared__ float sm[];
    float* k_s  = sm;
    float* q_s  = k_s + 64 * 512;
    float* vj_s = q_s + 64 * 32;
    __shared__ float redm[8][8];
    __shared__ float reds[8][8];
    __shared__ float redd[8][8];

    int b  = blockIdx.y;
    int u0 = blockIdx.x * 32;
    int tid = threadIdx.x;

    const float4* ksrc = (const float4*)(g_kt) + (size_t)b * (64 * NU / 4);
    float4* kdst = (float4*)k_s;
    for (int i = tid; i < 64 * NU / 4; i += 256) kdst[i] = ksrc[i];
    for (int i = tid; i < 64 * 32; i += 256) {
        int c = i >> 5, u = i & 31;
        q_s[c * 32 + u] = g_qt[(b * 64 + c) * NU + u0 + u];
    }
    for (int i = tid; i < 512; i += 256) vj_s[i] = g_vj[b * NU + i];
    __syncthreads();

    int g  = tid >> 6;
    int ug = g * 8;
    int vg = (tid & 63) * 8;
    float acc[8][8] = {};
    const float4* k4 = (const float4*)k_s;
    const float4* q4 = (const float4*)q_s;
    int kv_i = vg >> 2, qu_i = ug >> 2;
    #pragma unroll 4
    for (int kk = 0; kk < 64; kk++) {
        float4 kv0 = k4[kk * 128 + kv_i];
        float4 kv1 = k4[kk * 128 + kv_i + 1];
        float4 qv0 = q4[kk * 8 + qu_i];
        float4 qv1 = q4[kk * 8 + qu_i + 1];
        float qa[8] = {qv0.x, qv0.y, qv0.z, qv0.w, qv1.x, qv1.y, qv1.z, qv1.w};
        float kb[8] = {kv0.x, kv0.y, kv0.z, kv0.w, kv1.x, kv1.y, kv1.z, kv1.w};
        #pragma unroll
        for (int i = 0; i < 8; i++)
            #pragma unroll
            for (int j = 0; j < 8; j++)
                acc[i][j] += qa[i] * kb[j];
    }
    float rm[8];
    #pragma unroll
    for (int i = 0; i < 8; i++) {
        int u = ug + i;
        const float4* arow = (const float4*)(adj + (size_t)(u0 + u) * NU + vg);
        float4 a0 = arow[0], a1 = arow[1];
        acc[i][0] = acc[i][0] * 0.125f - (1.f - a0.x) * 500.f;
        acc[i][1] = acc[i][1] * 0.125f - (1.f - a0.y) * 500.f;
        acc[i][2] = acc[i][2] * 0.125f - (1.f - a0.z) * 500.f;
        acc[i][3] = acc[i][3] * 0.125f - (1.f - a0.w) * 500.f;
        acc[i][4] = acc[i][4] * 0.125f - (1.f - a1.x) * 500.f;
        acc[i][5] = acc[i][5] * 0.125f - (1.f - a1.y) * 500.f;
        acc[i][6] = acc[i][6] * 0.125f - (1.f - a1.z) * 500.f;
        acc[i][7] = acc[i][7] * 0.125f - (1.f - a1.w) * 500.f;
        float m = acc[i][0];
        #pragma unroll
        for (int j = 1; j < 8; j++) m = fmaxf(m, acc[i][j]);
        rm[i] = m;
    }
    int w = tid >> 5, lane = tid & 31;
    #pragma unroll
    for (int i = 0; i < 8; i++) {
        float m = rm[i];
        #pragma unroll
        for (int o = 16; o; o >>= 1) m = fmaxf(m, __shfl_xor_sync(0xffffffffu, m, o));
        if (lane == 0) redm[w][i] = m;
    }
    __syncthreads();
    #pragma unroll
    for (int i = 0; i < 8; i++) rm[i] = fmaxf(redm[g * 2][i], redm[g * 2 + 1][i]);

    float vjv[8];
    {
        const float4* v4 = (const float4*)(vj_s + vg);
        float4 v0 = v4[0], v1 = v4[1];
        vjv[0] = v0.x; vjv[1] = v0.y; vjv[2] = v0.z; vjv[3] = v0.w;
        vjv[4] = v1.x; vjv[5] = v1.y; vjv[6] = v1.z; vjv[7] = v1.w;
    }
    #pragma unroll
    for (int i = 0; i < 8; i++) {
        float s = 0.f, d = 0.f;
        #pragma unroll
        for (int j = 0; j < 8; j++) {
            float e = __expf(acc[i][j] - rm[i]);
            s += e;
            d += e * vjv[j];
        }
        #pragma unroll
        for (int o = 16; o; o >>= 1) {
            s += __shfl_xor_sync(0xffffffffu, s, o);
            d += __shfl_xor_sync(0xffffffffu, d, o);
        }
        if (lane == 0) { reds[w][i] = s; redd[w][i] = d; }
    }
    __syncthreads();
    if ((tid & 63) < 8) {
        int i = tid & 63;
        float s = reds[g * 2][i] + reds[g * 2 + 1][i];
        float d = redd[g * 2][i] + redd[g * 2 + 1][i];
        g_sj[(u0 + ug + i) * NBAT + b] = d / s;
    }
}

__global__ void k_nodealpha() {
    int idx = blockIdx.x * blockDim.x + threadIdx.x;
    if (idx >= NNODE * NBAT) return;
    int n = idx >> 3, b = idx & 7;
    int s = g_rowstart[n], e2 = g_rowstart[n + 1];
    if (s == e2) return;
    float si = g_si[n * NBAT + b];
    float m = -1e30f;
    for (int j = s; j < e2; j++) {
        int u = g_uperm[j];
        float a = si + g_sj[u * NBAT + b];
        a = (a > 0.f) ? a : 0.2f * a;
        g_alpha_p[j * NBAT + b] = a;
        m = fmaxf(m, a);
    }
    float sum = 0.f;
    for (int j = s; j < e2; j++) sum += __expf(g_alpha_p[j * NBAT + b] - m);
    float inv = 1.0f / (sum + 1e-16f);
    for (int j = s; j < e2; j++) {
        float v = __expf(g_alpha_p[j * NBAT + b] - m) * inv;
        g_alpha_p[j * NBAT + b] = v;
        g_alpha_e[g_perm[j] * NBAT + b] = v;
    }
}

__global__ void __launch_bounds__(512, 2) k_out1(const float* __restrict__ x,
                                                 const int* __restrict__ hi) {
    __shared__ int   nidx[256];
    __shared__ int   sb[2];
    __shared__ float a_s[256 * 8];
    __shared__ float4 part[4][128];
    int u = blockIdx.x;
    int tid = threadIdx.x;
    int is64 = g_idx64;
    if (tid < 2) sb[tid] = edgeLB(hi, u + tid, is64);
    __syncthreads();
    int start = sb[0], end = sb[1];
    float bn = (end > start) ? 1.0f / (float)(end - start) : 0.0f;

    int js = tid >> 7;
    int b  = (tid >> 4) & 7;
    int c4 = tid & 15;
    const float4* x4 = (const float4*)x;
    float4 acc = make_float4(0.f, 0.f, 0.f, 0.f);
    for (int s0 = start; s0 < end; s0 += 256) {
        int cnt = min(256, end - s0);
        __syncthreads();
        if (tid < cnt) nidx[tid] = nodeAt(hi, s0 + tid, is64);
        for (int i = tid; i < cnt * 8; i += 512) a_s[i] = g_alpha_e[s0 * 8 + i];
        __syncthreads();
        #pragma unroll 4
        for (int j = js; j < cnt; j += 4) {
            float a = a_s[j * 8 + b];
            float4 xv = x4[((size_t)b * NNODE + nidx[j]) * 16 + c4];
            acc.x += a * xv.x; acc.y += a * xv.y; acc.z += a * xv.z; acc.w += a * xv.w;
        }
    }
    part[js][b * 16 + c4] = acc;
    __syncthreads();
    if (tid < 128) {
        float4 p0 = part[0][tid], p1 = part[1][tid], p2 = part[2][tid], p3 = part[3][tid];
        float4 r;
        r.x = (p0.x + p1.x + p2.x + p3.x) * bn;
        r.y = (p0.y + p1.y + p2.y + p3.y) * bn;
        r.z = (p0.z + p1.z + p2.z + p3.z) * bn;
        r.w = (p0.w + p1.w + p2.w + p3.w) * bn;
        int bb = tid >> 4, cc = tid & 15;
        ((float4*)g_out1)[(u * 8 + bb) * 16 + cc] = r;
    }
}

__global__ void k_out2(float* __restrict__ out) {
    int idx = blockIdx.x * blockDim.x + threadIdx.x;
    int n  = idx >> 7;
    int b  = (idx >> 4) & 7;
    int c4 = idx & 15;
    if (n >= NNODE) return;
    int s = g_rowstart[n], e2 = g_rowstart[n + 1];
    const float4* o4 = (const float4*)g_out1;
    float4 acc = make_float4(0.f, 0.f, 0.f, 0.f);
    for (int j = s; j < e2; j++) {
        int u = g_uperm[j];
        float a = g_alpha_p[j * NBAT + b];
        float4 ov = o4[(u * 8 + b) * 16 + c4];
        acc.x += a * ov.x; acc.y += a * ov.y; acc.z += a * ov.z; acc.w += a * ov.w;
    }
    float D = (float)(e2 - s);
    acc.x *= D; acc.y *= D; acc.z *= D; acc.w *= D;
    ((float4*)out)[((size_t)b * NNODE + n) * 16 + c4] = acc;
}

extern "C" void kernel_launch(void* const* d_in, const int* in_sizes, int n_in,
                              void* d_out, int out_size) {
    const float* x   = (const float*)d_in[0];
    const float* Wq  = (const float*)d_in[1];
    const float* bq  = (const float*)d_in[2];
    const float* Wk  = (const float*)d_in[3];
    const float* bk  = (const float*)d_in[4];
    const float* Wv  = (const float*)d_in[5];
    const float* bv  = (const float*)d_in[6];
    const float* att = (const float*)d_in[7];
    const float* adj = (const float*)d_in[8];
    const int*   hi  = (const int*)d_in[9];
    float* out = (float*)d_out;

    static cudaStream_t s2 = nullptr;
    static cudaEvent_t ev0 = nullptr, ev2 = nullptr;
    if (s2 == nullptr) {
        cudaStreamCreateWithFlags(&s2, cudaStreamNonBlocking);
        cudaEventCreateWithFlags(&ev0, cudaEventDisableTiming);
        cudaEventCreateWithFlags(&ev2, cudaEventDisableTiming);
    }

    k_init<<<1, 64>>>(hi, att, Wv, bv);
    cudaEventRecord(ev0, 0);

    // side stream: CSR build + s_i, overlapped with aggqk/attn
    cudaStreamWaitEvent(s2, ev0, 0);
    k_zero<<<NSB, 256, 0, s2>>>();
    k_hist<<<NE / 256, 256, 0, s2>>>(hi);
    k_scan12<<<NSB, SCAN_BS, 0, s2>>>();
    k_scan3<<<NSB, SCAN_BS, 0, s2>>>();
    k_scatter<<<NE / 256, 256, 0, s2>>>(hi);
    k_si<<<(NNODE * NBAT + 255) / 256, 256, 0, s2>>>(x, att);
    cudaEventRecord(ev2, s2);

    // main stream: heavy compute chain
    k_aggqk<<<NU, 512>>>(x, hi, Wq, bq, Wk, bk);
    size_t attn_smem = (size_t)(64 * 512 + 64 * 32 + 512) * sizeof(float);
    cudaFuncSetAttribute(k_attn, cudaFuncAttributeMaxDynamicSharedMemorySize, (int)attn_smem);
    k_attn<<<dim3(16, 8), 256, attn_smem>>>(adj);

    cudaStreamWaitEvent(0, ev2, 0);
    k_nodealpha<<<(NNODE * NBAT + 255) / 256, 256>>>();
    k_out1<<<NU, 512>>>(x, hi);
    k_out2<<<(NNODE * 128 + 255) / 256, 256>>>(out);
}